// round 3
// baseline (speedup 1.0000x reference)
#include <cuda_runtime.h>

#define NN 100000
#define EE 1200000
#define GG 128
#define OUTC 320   // 64*(4+1)

// ---------------- scratch (static __device__, no allocation) ----------------
__device__ __align__(128) float g_h[NN * 64];
__device__ __align__(128) float g_agg[NN * 64];
__device__ __align__(128) float g_z1[NN * 64];
__device__ float g_pool[GG * OUTC];
__device__ int   g_cnt[GG];
__device__ float g_bnsum[64];
__device__ float g_bnsq[64];

// ---------------- per-graph node counts ----------------
__global__ void count_kernel(const int* __restrict__ batch) {
    int i = blockIdx.x * 256 + threadIdx.x;
    if (i < NN) atomicAdd(&g_cnt[batch[i]], 1);
}

// ---------------- edge scatter-add: agg[dst] += h[src] ----------------
// one thread per (edge, float4-chunk); 16 consecutive threads share an edge
__global__ void scatter_kernel(const int* __restrict__ ei) {
    int idx = blockIdx.x * 256 + threadIdx.x;   // grid covers exactly EE*16
    int e = idx >> 4, c = idx & 15;
    int src = ei[e];
    int dst = ei[EE + e];
    float4 v = ((const float4*)g_h)[(size_t)src * 16 + c];
    float* p = g_agg + (size_t)dst * 64 + c * 4;
    asm volatile("red.global.add.v4.f32 [%0], {%1,%2,%3,%4};"
                 :: "l"(p), "f"(v.x), "f"(v.y), "f"(v.z), "f"(v.w) : "memory");
}

#define FMA16(zk, base)                                                     \
    {                                                                       \
        const float4* wr = (const float4*)((base));                         \
        float4 w0 = wr[0], w1 = wr[1], w2 = wr[2], w3 = wr[3];              \
        acc[0]  += (zk)*w0.x; acc[1]  += (zk)*w0.y;                         \
        acc[2]  += (zk)*w0.z; acc[3]  += (zk)*w0.w;                         \
        acc[4]  += (zk)*w1.x; acc[5]  += (zk)*w1.y;                         \
        acc[6]  += (zk)*w1.z; acc[7]  += (zk)*w1.w;                         \
        acc[8]  += (zk)*w2.x; acc[9]  += (zk)*w2.y;                         \
        acc[10] += (zk)*w2.z; acc[11] += (zk)*w2.w;                         \
        acc[12] += (zk)*w3.x; acc[13] += (zk)*w3.y;                         \
        acc[14] += (zk)*w3.z; acc[15] += (zk)*w3.w;                         \
    }

// ---------------- GEMM1: z1 = (h+agg) @ W1 + b1, plus BN stats ----------------
// 64 rows/block, 256 threads: thread = (row, 16-col group)
__global__ void gemm1_kernel(const float* __restrict__ W, const float* __restrict__ b) {
    __shared__ float Ws[4096];
    __shared__ float Zs[64 * 65];
    int t = threadIdx.x;
    int row0 = blockIdx.x * 64;

#pragma unroll
    for (int i = 0; i < 16; i++) Ws[t + i * 256] = W[t + i * 256];
#pragma unroll
    for (int i = 0; i < 16; i++) {
        int e = t + i * 256;
        int r = e >> 6, k = e & 63;
        int gr = row0 + r;
        float v = 0.f;
        if (gr < NN) v = g_h[(size_t)gr * 64 + k] + g_agg[(size_t)gr * 64 + k];
        Zs[r * 65 + k] = v;
    }
    __syncthreads();

    int row = t >> 2;
    int cg = (t & 3) * 16;
    float acc[16];
#pragma unroll
    for (int j = 0; j < 16; j++) acc[j] = b[cg + j];
#pragma unroll
    for (int k = 0; k < 64; k++) {
        float zk = Zs[row * 65 + k];
        FMA16(zk, Ws + k * 64 + cg);
    }

    int gr = row0 + row;
    bool valid = gr < NN;
    if (valid) {
        float4* o = (float4*)(g_z1 + (size_t)gr * 64 + cg);
        o[0] = make_float4(acc[0], acc[1], acc[2], acc[3]);
        o[1] = make_float4(acc[4], acc[5], acc[6], acc[7]);
        o[2] = make_float4(acc[8], acc[9], acc[10], acc[11]);
        o[3] = make_float4(acc[12], acc[13], acc[14], acc[15]);
    }
    __syncthreads();
#pragma unroll
    for (int j = 0; j < 16; j++) Zs[row * 65 + cg + j] = valid ? acc[j] : 0.f;
    __syncthreads();

    if (t < 64) {
        float s = 0.f, q = 0.f;
#pragma unroll
        for (int r = 0; r < 64; r++) {
            float v = Zs[r * 65 + t];
            s += v;
            q += v * v;
        }
        atomicAdd(&g_bnsum[t], s);
        atomicAdd(&g_bnsq[t], q);
    }
}

// ---------------- GEMM2: h = relu(bn(z1)) @ W2 + b2, plus mean-pool ----------------
// BN=false is the embedding GEMM: h = x @ W_emb + b_emb (D == H == 64)
template <bool BN>
__global__ void gemm2_kernel(const float* __restrict__ in,
                             const float* __restrict__ W, const float* __restrict__ b,
                             const float* __restrict__ gamma, const float* __restrict__ beta,
                             const int* __restrict__ batch, int pool_off) {
    __shared__ float Ws[4096];
    __shared__ float Zs[64 * 65];
    __shared__ float sc[64], sh[64];
    __shared__ int sb[64];
    int t = threadIdx.x;
    int row0 = blockIdx.x * 64;

    if (t < 64) {
        int gr = row0 + t;
        sb[t] = (gr < NN) ? batch[gr] : -1;
        if (BN) {
            float mu = g_bnsum[t] * (1.f / NN);
            float var = g_bnsq[t] * (1.f / NN) - mu * mu;
            float rs = rsqrtf(var + 1e-5f);
            float s = gamma[t] * rs;
            sc[t] = s;
            sh[t] = beta[t] - mu * s;
        }
    }
#pragma unroll
    for (int i = 0; i < 16; i++) Ws[t + i * 256] = W[t + i * 256];
    __syncthreads();

#pragma unroll
    for (int i = 0; i < 16; i++) {
        int e = t + i * 256;
        int r = e >> 6, k = e & 63;
        int gr = row0 + r;
        float v = 0.f;
        if (gr < NN) {
            v = in[(size_t)gr * 64 + k];
            if (BN) v = fmaxf(v * sc[k] + sh[k], 0.f);
        }
        Zs[r * 65 + k] = v;
    }
    __syncthreads();

    int row = t >> 2;
    int cg = (t & 3) * 16;
    float acc[16];
#pragma unroll
    for (int j = 0; j < 16; j++) acc[j] = b[cg + j];
#pragma unroll
    for (int k = 0; k < 64; k++) {
        float zk = Zs[row * 65 + k];
        FMA16(zk, Ws + k * 64 + cg);
    }

    int gr = row0 + row;
    bool valid = gr < NN;
    if (valid) {
        float4* o = (float4*)(g_h + (size_t)gr * 64 + cg);
        o[0] = make_float4(acc[0], acc[1], acc[2], acc[3]);
        o[1] = make_float4(acc[4], acc[5], acc[6], acc[7]);
        o[2] = make_float4(acc[8], acc[9], acc[10], acc[11]);
        o[3] = make_float4(acc[12], acc[13], acc[14], acc[15]);
    }
    __syncthreads();
#pragma unroll
    for (int j = 0; j < 16; j++) Zs[row * 65 + cg + j] = valid ? acc[j] : 0.f;
    __syncthreads();

    // segmented mean-pool accumulation (batch is sorted -> few runs per block)
    if (t < 64) {
        float s = 0.f;
        int cur = sb[0];
        for (int r = 0; r < 64; r++) {
            int g2 = sb[r];
            if (g2 != cur) {
                if (cur >= 0) atomicAdd(&g_pool[cur * OUTC + pool_off + t], s);
                s = 0.f;
                cur = g2;
            }
            s += Zs[r * 65 + t];
        }
        if (cur >= 0) atomicAdd(&g_pool[cur * OUTC + pool_off + t], s);
    }
}

__global__ void finalize_kernel(float* __restrict__ out) {
    int i = blockIdx.x * 256 + threadIdx.x;
    if (i < GG * OUTC) {
        int g = i / OUTC;
        float c = (float)max(g_cnt[g], 1);
        out[i] = g_pool[i] / c;
    }
}

// ---------------- host ----------------
extern "C" void kernel_launch(void* const* d_in, const int* in_sizes, int n_in,
                              void* d_out, int out_size) {
    const float* x     = (const float*)d_in[0];
    const int*   ei    = (const int*)d_in[1];
    const int*   batch = (const int*)d_in[2];
    const float* W_emb = (const float*)d_in[3];
    const float* b_emb = (const float*)d_in[4];
    const float* W1    = (const float*)d_in[5];
    const float* b1    = (const float*)d_in[6];
    const float* gamma = (const float*)d_in[7];
    const float* beta  = (const float*)d_in[8];
    const float* W2    = (const float*)d_in[9];
    const float* b2    = (const float*)d_in[10];
    float* out = (float*)d_out;

    void *p_pool, *p_cnt, *p_agg, *p_bnsum, *p_bnsq, *p_z1;
    cudaGetSymbolAddress(&p_pool, g_pool);
    cudaGetSymbolAddress(&p_cnt, g_cnt);
    cudaGetSymbolAddress(&p_agg, g_agg);
    cudaGetSymbolAddress(&p_bnsum, g_bnsum);
    cudaGetSymbolAddress(&p_bnsq, g_bnsq);
    cudaGetSymbolAddress(&p_z1, g_z1);

    cudaMemsetAsync(p_pool, 0, GG * OUTC * sizeof(float), 0);
    cudaMemsetAsync(p_cnt, 0, GG * sizeof(int), 0);

    count_kernel<<<(NN + 255) / 256, 256>>>(batch);

    const int GB = (NN + 63) / 64;  // 1563 row-tiles

    // embedding GEMM + pool into columns [0,64)
    gemm2_kernel<false><<<GB, 256>>>(x, W_emb, b_emb, nullptr, nullptr, batch, 0);

    for (int l = 0; l < 4; l++) {
        cudaMemsetAsync(p_agg, 0, (size_t)NN * 64 * sizeof(float), 0);
        scatter_kernel<<<(EE * 16) / 256, 256>>>(ei);
        cudaMemsetAsync(p_bnsum, 0, 64 * sizeof(float), 0);
        cudaMemsetAsync(p_bnsq, 0, 64 * sizeof(float), 0);
        gemm1_kernel<<<GB, 256>>>(W1 + l * 4096, b1 + l * 64);
        gemm2_kernel<true><<<GB, 256>>>((const float*)p_z1, W2 + l * 4096, b2 + l * 64,
                                        gamma + l * 64, beta + l * 64, batch,
                                        (l + 1) * 64);
    }

    finalize_kernel<<<(GG * OUTC + 255) / 256, 256>>>(out);
}

// round 6
// speedup vs baseline: 1.8020x; 1.8020x over previous
#include <cuda_runtime.h>

#define NN 100000
#define EE 1200000
#define GG 128
#define OUTC 320   // 64*(4+1)
#define ROWS 96    // rows per GEMM block
#define ZSTR 68    // smem row stride (floats)

// ---------------- scratch (static __device__, no allocation) ----------------
__device__ __align__(128) float g_h[NN * 64];
__device__ __align__(128) float g_agg[NN * 64];
__device__ __align__(128) float g_z1[NN * 64];
__device__ float g_pool[GG * OUTC];
__device__ int   g_cnt[GG];
__device__ float g_bnsum[64];
__device__ float g_bnsq[64];

// ---------------- per-graph node counts ----------------
__global__ void count_kernel(const int* __restrict__ batch) {
    int i = blockIdx.x * 256 + threadIdx.x;
    if (i < NN) atomicAdd(&g_cnt[batch[i]], 1);
}

// ---------------- edge scatter-add: agg[dst] += h[src] ----------------
__global__ void scatter_kernel(const int* __restrict__ ei) {
    int idx = blockIdx.x * 256 + threadIdx.x;   // grid covers exactly EE*16
    int e = idx >> 4, c = idx & 15;
    int src = ei[e];
    int dst = ei[EE + e];
    float4 v = ((const float4*)g_h)[(size_t)src * 16 + c];
    float* p = g_agg + (size_t)dst * 64 + c * 4;
    asm volatile("red.global.add.v4.f32 [%0], {%1,%2,%3,%4};"
                 :: "l"(p), "f"(v.x), "f"(v.y), "f"(v.z), "f"(v.w) : "memory");
}

// 8 FMAs of one z-scalar against a row-of-8 W, into acc row j
// (param named zv to avoid colliding with float4 member .z)
#define FMA8(j, zv, w0, w1)                                   \
    acc[j][0] += (zv) * (w0).x; acc[j][1] += (zv) * (w0).y;   \
    acc[j][2] += (zv) * (w0).z; acc[j][3] += (zv) * (w0).w;   \
    acc[j][4] += (zv) * (w1).x; acc[j][5] += (zv) * (w1).y;   \
    acc[j][6] += (zv) * (w1).z; acc[j][7] += (zv) * (w1).w;

// ---------------- GEMM1: z1 = (h+agg) @ W1 + b1, plus BN stats ----------------
// 96 rows x 64 cols per block, 256 threads, thread tile = 3 rows x 8 cols
__global__ __launch_bounds__(256) void gemm1_kernel(const float* __restrict__ W,
                                                    const float* __restrict__ b) {
    __shared__ float Ws[4096];
    __shared__ float Zs[ROWS * ZSTR];
    int t = threadIdx.x;
    int row0 = blockIdx.x * ROWS;

    const float4* Wg = (const float4*)W;
    float4* Ws4 = (float4*)Ws;
#pragma unroll
    for (int i = 0; i < 4; i++) Ws4[t + i * 256] = Wg[t + i * 256];

#pragma unroll
    for (int i = 0; i < 6; i++) {
        int e = t + i * 256;               // 96*16 = 1536 float4s
        int r = e >> 4, c4 = e & 15;
        int gr = row0 + r;
        float4 v = make_float4(0.f, 0.f, 0.f, 0.f);
        if (gr < NN) {
            float4 a  = ((const float4*)g_h)[(size_t)gr * 16 + c4];
            float4 bb = ((const float4*)g_agg)[(size_t)gr * 16 + c4];
            v = make_float4(a.x + bb.x, a.y + bb.y, a.z + bb.z, a.w + bb.w);
        }
        ((float4*)(Zs + r * ZSTR))[c4] = v;
    }
    __syncthreads();

    int cw = t & 7;            // col group: cols cw*8 .. cw*8+7
    int rowb = (t >> 3) * 3;   // 32 row groups x 3 rows = 96
    float acc[3][8];
#pragma unroll
    for (int j = 0; j < 3; j++)
#pragma unroll
        for (int c = 0; c < 8; c++) acc[j][c] = b[cw * 8 + c];

#pragma unroll 8
    for (int k = 0; k < 64; k++) {
        float4 w0 = ((const float4*)Ws)[k * 16 + cw * 2];
        float4 w1 = ((const float4*)Ws)[k * 16 + cw * 2 + 1];
        float za = Zs[(rowb + 0) * ZSTR + k];
        float zb = Zs[(rowb + 1) * ZSTR + k];
        float zc = Zs[(rowb + 2) * ZSTR + k];
        FMA8(0, za, w0, w1);
        FMA8(1, zb, w0, w1);
        FMA8(2, zc, w0, w1);
    }
    __syncthreads();   // done reading Zs; reuse it for outputs

#pragma unroll
    for (int j = 0; j < 3; j++) {
        int r = rowb + j;
        int gr = row0 + r;
        float4 o0 = make_float4(acc[j][0], acc[j][1], acc[j][2], acc[j][3]);
        float4 o1 = make_float4(acc[j][4], acc[j][5], acc[j][6], acc[j][7]);
        if (gr < NN) {
            float4* og = (float4*)(g_z1 + (size_t)gr * 64 + cw * 8);
            og[0] = o0; og[1] = o1;
        } else {
            o0 = make_float4(0.f, 0.f, 0.f, 0.f);
            o1 = o0;
        }
        float4* os = (float4*)(Zs + r * ZSTR + cw * 8);
        os[0] = o0; os[1] = o1;
    }
    __syncthreads();

    if (t < 64) {
        float s = 0.f, q = 0.f;
#pragma unroll 8
        for (int r = 0; r < ROWS; r++) {
            float v = Zs[r * ZSTR + t];
            s += v;
            q += v * v;
        }
        atomicAdd(&g_bnsum[t], s);
        atomicAdd(&g_bnsq[t], q);
    }
}

// ---------------- GEMM2: h = relu(bn(z1)) @ W2 + b2, plus mean-pool ----------------
// BN=false is the embedding GEMM: h = x @ W_emb + b_emb
template <bool BN>
__global__ __launch_bounds__(256) void gemm2_kernel(const float* __restrict__ in,
                             const float* __restrict__ W, const float* __restrict__ b,
                             const float* __restrict__ gamma, const float* __restrict__ beta,
                             const int* __restrict__ batch, int pool_off) {
    __shared__ float Ws[4096];
    __shared__ float Zs[ROWS * ZSTR];
    __shared__ float sc[64], sh[64];
    __shared__ int sb[ROWS];
    int t = threadIdx.x;
    int row0 = blockIdx.x * ROWS;

    if (t < ROWS) {
        int gr = row0 + t;
        sb[t] = (gr < NN) ? batch[gr] : -1;
    }
    if (t < 64 && BN) {
        float mu = g_bnsum[t] * (1.f / NN);
        float var = g_bnsq[t] * (1.f / NN) - mu * mu;
        float rs = rsqrtf(var + 1e-5f);
        float s = gamma[t] * rs;
        sc[t] = s;
        sh[t] = beta[t] - mu * s;
    }
    const float4* Wg = (const float4*)W;
    float4* Ws4 = (float4*)Ws;
#pragma unroll
    for (int i = 0; i < 4; i++) Ws4[t + i * 256] = Wg[t + i * 256];
    __syncthreads();

#pragma unroll
    for (int i = 0; i < 6; i++) {
        int e = t + i * 256;
        int r = e >> 4, c4 = e & 15;
        int gr = row0 + r;
        float4 v = make_float4(0.f, 0.f, 0.f, 0.f);
        if (gr < NN) {
            v = ((const float4*)in)[(size_t)gr * 16 + c4];
            if (BN) {
                int k = c4 * 4;
                v.x = fmaxf(v.x * sc[k]     + sh[k],     0.f);
                v.y = fmaxf(v.y * sc[k + 1] + sh[k + 1], 0.f);
                v.z = fmaxf(v.z * sc[k + 2] + sh[k + 2], 0.f);
                v.w = fmaxf(v.w * sc[k + 3] + sh[k + 3], 0.f);
            }
        }
        ((float4*)(Zs + r * ZSTR))[c4] = v;
    }
    __syncthreads();

    int cw = t & 7;
    int rowb = (t >> 3) * 3;
    float acc[3][8];
#pragma unroll
    for (int j = 0; j < 3; j++)
#pragma unroll
        for (int c = 0; c < 8; c++) acc[j][c] = b[cw * 8 + c];

#pragma unroll 8
    for (int k = 0; k < 64; k++) {
        float4 w0 = ((const float4*)Ws)[k * 16 + cw * 2];
        float4 w1 = ((const float4*)Ws)[k * 16 + cw * 2 + 1];
        float za = Zs[(rowb + 0) * ZSTR + k];
        float zb = Zs[(rowb + 1) * ZSTR + k];
        float zc = Zs[(rowb + 2) * ZSTR + k];
        FMA8(0, za, w0, w1);
        FMA8(1, zb, w0, w1);
        FMA8(2, zc, w0, w1);
    }
    __syncthreads();

#pragma unroll
    for (int j = 0; j < 3; j++) {
        int r = rowb + j;
        int gr = row0 + r;
        float4 o0 = make_float4(acc[j][0], acc[j][1], acc[j][2], acc[j][3]);
        float4 o1 = make_float4(acc[j][4], acc[j][5], acc[j][6], acc[j][7]);
        if (gr < NN) {
            float4* og = (float4*)(g_h + (size_t)gr * 64 + cw * 8);
            og[0] = o0; og[1] = o1;
        } else {
            o0 = make_float4(0.f, 0.f, 0.f, 0.f);
            o1 = o0;
        }
        float4* os = (float4*)(Zs + r * ZSTR + cw * 8);
        os[0] = o0; os[1] = o1;
    }
    __syncthreads();

    // segmented mean-pool accumulation (batch is sorted -> few runs per block)
    if (t < 64) {
        float s = 0.f;
        int cur = sb[0];
        for (int r = 0; r < ROWS; r++) {
            int g2 = sb[r];
            if (g2 != cur) {
                if (cur >= 0) atomicAdd(&g_pool[cur * OUTC + pool_off + t], s);
                s = 0.f;
                cur = g2;
            }
            s += Zs[r * ZSTR + t];
        }
        if (cur >= 0) atomicAdd(&g_pool[cur * OUTC + pool_off + t], s);
    }
}

__global__ void finalize_kernel(float* __restrict__ out) {
    int i = blockIdx.x * 256 + threadIdx.x;
    if (i < GG * OUTC) {
        int g = i / OUTC;
        float c = (float)max(g_cnt[g], 1);
        out[i] = g_pool[i] / c;
    }
}

// ---------------- host ----------------
extern "C" void kernel_launch(void* const* d_in, const int* in_sizes, int n_in,
                              void* d_out, int out_size) {
    const float* x     = (const float*)d_in[0];
    const int*   ei    = (const int*)d_in[1];
    const int*   batch = (const int*)d_in[2];
    const float* W_emb = (const float*)d_in[3];
    const float* b_emb = (const float*)d_in[4];
    const float* W1    = (const float*)d_in[5];
    const float* b1    = (const float*)d_in[6];
    const float* gamma = (const float*)d_in[7];
    const float* beta  = (const float*)d_in[8];
    const float* W2    = (const float*)d_in[9];
    const float* b2    = (const float*)d_in[10];
    float* out = (float*)d_out;

    void *p_pool, *p_cnt, *p_agg, *p_bnsum, *p_bnsq, *p_z1;
    cudaGetSymbolAddress(&p_pool, g_pool);
    cudaGetSymbolAddress(&p_cnt, g_cnt);
    cudaGetSymbolAddress(&p_agg, g_agg);
    cudaGetSymbolAddress(&p_bnsum, g_bnsum);
    cudaGetSymbolAddress(&p_bnsq, g_bnsq);
    cudaGetSymbolAddress(&p_z1, g_z1);

    cudaMemsetAsync(p_pool, 0, GG * OUTC * sizeof(float), 0);
    cudaMemsetAsync(p_cnt, 0, GG * sizeof(int), 0);

    count_kernel<<<(NN + 255) / 256, 256>>>(batch);

    const int GB = (NN + ROWS - 1) / ROWS;  // 1042 row-tiles

    // embedding GEMM + pool into columns [0,64)
    gemm2_kernel<false><<<GB, 256>>>(x, W_emb, b_emb, nullptr, nullptr, batch, 0);

    for (int l = 0; l < 4; l++) {
        cudaMemsetAsync(p_agg, 0, (size_t)NN * 64 * sizeof(float), 0);
        scatter_kernel<<<(EE * 16) / 256, 256>>>(ei);
        cudaMemsetAsync(p_bnsum, 0, 64 * sizeof(float), 0);
        cudaMemsetAsync(p_bnsq, 0, 64 * sizeof(float), 0);
        gemm1_kernel<<<GB, 256>>>(W1 + l * 4096, b1 + l * 64);
        gemm2_kernel<true><<<GB, 256>>>((const float*)p_z1, W2 + l * 4096, b2 + l * 64,
                                        gamma + l * 64, beta + l * 64, batch,
                                        (l + 1) * 64);
    }

    finalize_kernel<<<(GG * OUTC + 255) / 256, 256>>>(out);
}

// round 7
// speedup vs baseline: 2.0578x; 1.1419x over previous
#include <cuda_runtime.h>

#define NN 100000
#define EE 1200000
#define GG 128
#define OUTC 320        // 64*(4+1)
#define ROWS 128        // rows per GEMM block
#define GT 128          // threads per GEMM block
#define SMEM_GEMM 50176 // (4096 + 8192 + 64 + 64 + 128) * 4 bytes

typedef unsigned long long u64;

// ---------------- scratch (static __device__, no allocation) ----------------
__device__ __align__(128) float g_h[NN * 64];
__device__ __align__(128) float g_agg[NN * 64];
__device__ __align__(128) float g_z1[NN * 64];
__device__ float g_pool[GG * OUTC];
__device__ int   g_cnt[GG];
__device__ float g_bnsum[64];
__device__ float g_bnsq[64];

// ---------------- packed f32x2 helpers ----------------
__device__ __forceinline__ u64 pack2(float x, float y) {
    u64 r; asm("mov.b64 %0, {%1, %2};" : "=l"(r) : "f"(x), "f"(y)); return r;
}
__device__ __forceinline__ void ffma2(u64& d, u64 a, u64 b) {
    asm("fma.rn.f32x2 %0, %1, %2, %0;" : "+l"(d) : "l"(a), "l"(b));
}
__device__ __forceinline__ float2 unpack2(u64 v) {
    float2 f; asm("mov.b64 {%0, %1}, %2;" : "=f"(f.x), "=f"(f.y) : "l"(v)); return f;
}

// ---------------- per-graph node counts ----------------
__global__ void count_kernel(const int* __restrict__ batch) {
    int i = blockIdx.x * 256 + threadIdx.x;
    if (i < NN) atomicAdd(&g_cnt[batch[i]], 1);
}

// ---------------- edge scatter-add: agg[dst] += h[src] ----------------
__global__ void scatter_kernel(const int* __restrict__ ei) {
    int idx = blockIdx.x * 256 + threadIdx.x;   // grid covers exactly EE*16
    int e = idx >> 4, c = idx & 15;
    int src = ei[e];
    int dst = ei[EE + e];
    float4 v = ((const float4*)g_h)[(size_t)src * 16 + c];
    float* p = g_agg + (size_t)dst * 64 + c * 4;
    asm volatile("red.global.add.v4.f32 [%0], {%1,%2,%3,%4};"
                 :: "l"(p), "f"(v.x), "f"(v.y), "f"(v.z), "f"(v.w) : "memory");
}

// Zs layout: row r occupies floats [r*64, r*64+64), column k stored at
// slot ((k + 4*(r>>3)) & 63). Rotation is a multiple of 4 floats -> float4
// accesses stay aligned; the 4 row-groups of a warp land on banks {0,4,8,12}.

// ---------------- GEMM1: z1 = (h+agg) @ W1 + b1, plus BN stats ----------------
// 128 rows x 64 cols per block, 128 threads, thread tile = 8 rows x 8 cols
__global__ __launch_bounds__(GT, 4) void gemm1_kernel(const float* __restrict__ W,
                                                      const float* __restrict__ b) {
    extern __shared__ float smp[];
    float* Ws = smp;          // 4096 floats
    float* Zs = smp + 4096;   // 8192 floats
    int t = threadIdx.x;
    int row0 = blockIdx.x * ROWS;

    const float4* Wg = (const float4*)W;
    float4* Ws4 = (float4*)Ws;
#pragma unroll
    for (int i = 0; i < 8; i++) Ws4[t + i * GT] = Wg[t + i * GT];

#pragma unroll
    for (int i = 0; i < 16; i++) {
        int e = t + i * GT;                // 128*16 = 2048 float4s
        int r = e >> 4, c4 = e & 15;
        int gr = row0 + r;
        float4 v = make_float4(0.f, 0.f, 0.f, 0.f);
        if (gr < NN) {
            float4 a  = ((const float4*)g_h)[(size_t)gr * 16 + c4];
            float4 bb = ((const float4*)g_agg)[(size_t)gr * 16 + c4];
            v = make_float4(a.x + bb.x, a.y + bb.y, a.z + bb.z, a.w + bb.w);
        }
        ((float4*)(Zs + r * 64))[(c4 + (r >> 3)) & 15] = v;
    }
    __syncthreads();

    int cw = t & 7;            // col group: cols cw*8 .. cw*8+7
    int g  = t >> 3;           // row group: rows g*8 .. g*8+7
    int rowb = g * 8;
    u64 acc[8][4];
#pragma unroll
    for (int c = 0; c < 4; c++) {
        u64 bp = pack2(b[cw * 8 + c * 2], b[cw * 8 + c * 2 + 1]);
#pragma unroll
        for (int j = 0; j < 8; j++) acc[j][c] = bp;
    }

    const ulonglong2* Wsu = (const ulonglong2*)Ws;   // 16 units per k-row
#pragma unroll 8
    for (int k = 0; k < 64; k++) {
        ulonglong2 wa = Wsu[k * 16 + cw * 2];        // cols cw*8..+3 (2 pairs)
        ulonglong2 wb = Wsu[k * 16 + cw * 2 + 1];    // cols cw*8+4..+7
        int kk = (k + 4 * g) & 63;
#pragma unroll
        for (int j = 0; j < 8; j++) {
            float z = Zs[(rowb + j) * 64 + kk];
            u64 zz = pack2(z, z);
            ffma2(acc[j][0], zz, wa.x);
            ffma2(acc[j][1], zz, wa.y);
            ffma2(acc[j][2], zz, wb.x);
            ffma2(acc[j][3], zz, wb.y);
        }
    }
    __syncthreads();   // done reading Zs; reuse it for outputs

#pragma unroll
    for (int j = 0; j < 8; j++) {
        int r = rowb + j;
        int gr = row0 + r;
        float2 p0 = unpack2(acc[j][0]), p1 = unpack2(acc[j][1]);
        float2 p2 = unpack2(acc[j][2]), p3 = unpack2(acc[j][3]);
        float4 o0 = make_float4(p0.x, p0.y, p1.x, p1.y);
        float4 o1 = make_float4(p2.x, p2.y, p3.x, p3.y);
        if (gr < NN) {
            float4* og = (float4*)(g_z1 + (size_t)gr * 64 + cw * 8);
            og[0] = o0; og[1] = o1;
        } else {
            o0 = make_float4(0.f, 0.f, 0.f, 0.f);
            o1 = o0;
        }
        float4* zr = (float4*)(Zs + r * 64);
        zr[(cw * 2 + g) & 15]     = o0;
        zr[(cw * 2 + 1 + g) & 15] = o1;
    }
    __syncthreads();

    if (t < 64) {
        float s = 0.f, q = 0.f;
#pragma unroll 8
        for (int r = 0; r < ROWS; r++) {
            float v = Zs[r * 64 + ((t + 4 * (r >> 3)) & 63)];
            s += v;
            q += v * v;
        }
        atomicAdd(&g_bnsum[t], s);
        atomicAdd(&g_bnsq[t], q);
    }
}

// ---------------- GEMM2: h = relu(bn(z1)) @ W2 + b2, plus mean-pool ----------------
// BN=false is the embedding GEMM: h = x @ W_emb + b_emb
template <bool BN>
__global__ __launch_bounds__(GT, 4) void gemm2_kernel(const float* __restrict__ in,
                             const float* __restrict__ W, const float* __restrict__ b,
                             const float* __restrict__ gamma, const float* __restrict__ beta,
                             const int* __restrict__ batch, int pool_off) {
    extern __shared__ float smp[];
    float* Ws = smp;            // 4096
    float* Zs = smp + 4096;     // 8192
    float* sc = smp + 12288;    // 64
    float* sh = smp + 12352;    // 64
    int*   sb = (int*)(smp + 12416);  // 128
    int t = threadIdx.x;
    int row0 = blockIdx.x * ROWS;

    {
        int gr = row0 + t;
        sb[t] = (gr < NN) ? batch[gr] : -1;
    }
    if (t < 64 && BN) {
        float mu = g_bnsum[t] * (1.f / NN);
        float var = g_bnsq[t] * (1.f / NN) - mu * mu;
        float rs = rsqrtf(var + 1e-5f);
        float s = gamma[t] * rs;
        sc[t] = s;
        sh[t] = beta[t] - mu * s;
    }
    const float4* Wg = (const float4*)W;
    float4* Ws4 = (float4*)Ws;
#pragma unroll
    for (int i = 0; i < 8; i++) Ws4[t + i * GT] = Wg[t + i * GT];
    __syncthreads();

#pragma unroll
    for (int i = 0; i < 16; i++) {
        int e = t + i * GT;
        int r = e >> 4, c4 = e & 15;
        int gr = row0 + r;
        float4 v = make_float4(0.f, 0.f, 0.f, 0.f);
        if (gr < NN) {
            v = ((const float4*)in)[(size_t)gr * 16 + c4];
            if (BN) {
                int k = c4 * 4;
                v.x = fmaxf(v.x * sc[k]     + sh[k],     0.f);
                v.y = fmaxf(v.y * sc[k + 1] + sh[k + 1], 0.f);
                v.z = fmaxf(v.z * sc[k + 2] + sh[k + 2], 0.f);
                v.w = fmaxf(v.w * sc[k + 3] + sh[k + 3], 0.f);
            }
        }
        ((float4*)(Zs + r * 64))[(c4 + (r >> 3)) & 15] = v;
    }
    __syncthreads();

    int cw = t & 7;
    int g  = t >> 3;
    int rowb = g * 8;
    u64 acc[8][4];
#pragma unroll
    for (int c = 0; c < 4; c++) {
        u64 bp = pack2(b[cw * 8 + c * 2], b[cw * 8 + c * 2 + 1]);
#pragma unroll
        for (int j = 0; j < 8; j++) acc[j][c] = bp;
    }

    const ulonglong2* Wsu = (const ulonglong2*)Ws;
#pragma unroll 8
    for (int k = 0; k < 64; k++) {
        ulonglong2 wa = Wsu[k * 16 + cw * 2];
        ulonglong2 wb = Wsu[k * 16 + cw * 2 + 1];
        int kk = (k + 4 * g) & 63;
#pragma unroll
        for (int j = 0; j < 8; j++) {
            float z = Zs[(rowb + j) * 64 + kk];
            u64 zz = pack2(z, z);
            ffma2(acc[j][0], zz, wa.x);
            ffma2(acc[j][1], zz, wa.y);
            ffma2(acc[j][2], zz, wb.x);
            ffma2(acc[j][3], zz, wb.y);
        }
    }
    __syncthreads();

#pragma unroll
    for (int j = 0; j < 8; j++) {
        int r = rowb + j;
        int gr = row0 + r;
        float2 p0 = unpack2(acc[j][0]), p1 = unpack2(acc[j][1]);
        float2 p2 = unpack2(acc[j][2]), p3 = unpack2(acc[j][3]);
        float4 o0 = make_float4(p0.x, p0.y, p1.x, p1.y);
        float4 o1 = make_float4(p2.x, p2.y, p3.x, p3.y);
        if (gr < NN) {
            float4* og = (float4*)(g_h + (size_t)gr * 64 + cw * 8);
            og[0] = o0; og[1] = o1;
        } else {
            o0 = make_float4(0.f, 0.f, 0.f, 0.f);
            o1 = o0;
        }
        float4* zr = (float4*)(Zs + r * 64);
        zr[(cw * 2 + g) & 15]     = o0;
        zr[(cw * 2 + 1 + g) & 15] = o1;
    }
    __syncthreads();

    // segmented mean-pool accumulation (batch is sorted -> few runs per block)
    if (t < 64) {
        float s = 0.f;
        int cur = sb[0];
        for (int r = 0; r < ROWS; r++) {
            int g2 = sb[r];
            if (g2 != cur) {
                if (cur >= 0) atomicAdd(&g_pool[cur * OUTC + pool_off + t], s);
                s = 0.f;
                cur = g2;
            }
            s += Zs[r * 64 + ((t + 4 * (r >> 3)) & 63)];
        }
        if (cur >= 0) atomicAdd(&g_pool[cur * OUTC + pool_off + t], s);
    }
}

__global__ void finalize_kernel(float* __restrict__ out) {
    int i = blockIdx.x * 256 + threadIdx.x;
    if (i < GG * OUTC) {
        int g = i / OUTC;
        float c = (float)max(g_cnt[g], 1);
        out[i] = g_pool[i] / c;
    }
}

// ---------------- host ----------------
extern "C" void kernel_launch(void* const* d_in, const int* in_sizes, int n_in,
                              void* d_out, int out_size) {
    const float* x     = (const float*)d_in[0];
    const int*   ei    = (const int*)d_in[1];
    const int*   batch = (const int*)d_in[2];
    const float* W_emb = (const float*)d_in[3];
    const float* b_emb = (const float*)d_in[4];
    const float* W1    = (const float*)d_in[5];
    const float* b1    = (const float*)d_in[6];
    const float* gamma = (const float*)d_in[7];
    const float* beta  = (const float*)d_in[8];
    const float* W2    = (const float*)d_in[9];
    const float* b2    = (const float*)d_in[10];
    float* out = (float*)d_out;

    cudaFuncSetAttribute(gemm1_kernel, cudaFuncAttributeMaxDynamicSharedMemorySize, SMEM_GEMM);
    cudaFuncSetAttribute(gemm2_kernel<false>, cudaFuncAttributeMaxDynamicSharedMemorySize, SMEM_GEMM);
    cudaFuncSetAttribute(gemm2_kernel<true>, cudaFuncAttributeMaxDynamicSharedMemorySize, SMEM_GEMM);

    void *p_pool, *p_cnt, *p_agg, *p_bnsum, *p_bnsq, *p_z1;
    cudaGetSymbolAddress(&p_pool, g_pool);
    cudaGetSymbolAddress(&p_cnt, g_cnt);
    cudaGetSymbolAddress(&p_agg, g_agg);
    cudaGetSymbolAddress(&p_bnsum, g_bnsum);
    cudaGetSymbolAddress(&p_bnsq, g_bnsq);
    cudaGetSymbolAddress(&p_z1, g_z1);

    cudaMemsetAsync(p_pool, 0, GG * OUTC * sizeof(float), 0);
    cudaMemsetAsync(p_cnt, 0, GG * sizeof(int), 0);

    count_kernel<<<(NN + 255) / 256, 256>>>(batch);

    const int GB = (NN + ROWS - 1) / ROWS;  // 782 row-tiles

    // embedding GEMM + pool into columns [0,64)
    gemm2_kernel<false><<<GB, GT, SMEM_GEMM>>>(x, W_emb, b_emb, nullptr, nullptr, batch, 0);

    for (int l = 0; l < 4; l++) {
        cudaMemsetAsync(p_agg, 0, (size_t)NN * 64 * sizeof(float), 0);
        scatter_kernel<<<(EE * 16) / 256, 256>>>(ei);
        cudaMemsetAsync(p_bnsum, 0, 64 * sizeof(float), 0);
        cudaMemsetAsync(p_bnsq, 0, 64 * sizeof(float), 0);
        gemm1_kernel<<<GB, GT, SMEM_GEMM>>>(W1 + l * 4096, b1 + l * 64);
        gemm2_kernel<true><<<GB, GT, SMEM_GEMM>>>((const float*)p_z1, W2 + l * 4096, b2 + l * 64,
                                        gamma + l * 64, beta + l * 64, batch,
                                        (l + 1) * 64);
    }

    finalize_kernel<<<(GG * OUTC + 255) / 256, 256>>>(out);
}

// round 8
// speedup vs baseline: 2.3535x; 1.1437x over previous
#include <cuda_runtime.h>

#define NN 100000
#define EE 1200000
#define GG 128
#define OUTC 320        // 64*(4+1)
#define ROWS 64         // rows per GEMM block
#define GT 128          // threads per GEMM block
#define SMEM_G 33536    // (4096 + 4096 + 64 + 64 + 64) floats * 4 + pad
#define NB 98           // scan blocks = ceil(NN/1024)

typedef unsigned long long u64;

// ---------------- scratch (static __device__, no allocation) ----------------
__device__ __align__(128) float g_h[NN * 64];
__device__ __align__(128) float g_agg[NN * 64];
__device__ __align__(128) float g_z1[NN * 64];
__device__ int   g_esrc[EE];
__device__ int   g_rowptr[NN + 1];
__device__ int   g_cursor[NN];
__device__ int   g_deg[NN];
__device__ int   g_bsum[NB];
__device__ float g_pool[GG * OUTC];
__device__ int   g_cnt[GG];
__device__ float g_bnsum[64];
__device__ float g_bnsq[64];

// ---------------- packed f32x2 helpers ----------------
__device__ __forceinline__ u64 pack2(float x, float y) {
    u64 r; asm("mov.b64 %0, {%1, %2};" : "=l"(r) : "f"(x), "f"(y)); return r;
}
__device__ __forceinline__ void ffma2(u64& d, u64 a, u64 b) {
    asm("fma.rn.f32x2 %0, %1, %2, %0;" : "+l"(d) : "l"(a), "l"(b));
}
__device__ __forceinline__ float2 unpack2(u64 v) {
    float2 f; asm("mov.b64 {%0, %1}, %2;" : "=f"(f.x), "=f"(f.y) : "l"(v)); return f;
}

// ---------------- per-graph node counts ----------------
__global__ void count_kernel(const int* __restrict__ batch) {
    int i = blockIdx.x * 256 + threadIdx.x;
    if (i < NN) atomicAdd(&g_cnt[batch[i]], 1);
}

// ---------------- CSR build ----------------
__global__ void deg_kernel(const int* __restrict__ ei) {
    int e = blockIdx.x * 256 + threadIdx.x;
    if (e < EE) atomicAdd(&g_deg[ei[EE + e]], 1);
}

__global__ void scan1_kernel() {
    __shared__ int s[1024];
    int t = threadIdx.x;
    int i = blockIdx.x * 1024 + t;
    int x = (i < NN) ? g_deg[i] : 0;
    s[t] = x;
    __syncthreads();
#pragma unroll
    for (int off = 1; off < 1024; off <<= 1) {
        int v = (t >= off) ? s[t - off] : 0;
        __syncthreads();
        s[t] += v;
        __syncthreads();
    }
    if (i < NN) g_rowptr[i] = s[t] - x;      // exclusive, partial
    if (t == 1023) g_bsum[blockIdx.x] = s[1023];
}

__global__ void scan2_kernel() {
    if (threadIdx.x == 0) {
        int run = 0;
        for (int b = 0; b < NB; b++) { int v = g_bsum[b]; g_bsum[b] = run; run += v; }
    }
}

__global__ void scan3_kernel() {
    int i = blockIdx.x * 256 + threadIdx.x;
    if (i < NN) {
        int v = g_rowptr[i] + g_bsum[i >> 10];
        g_rowptr[i] = v;
        g_cursor[i] = v;
    }
    if (i == 0) g_rowptr[NN] = EE;
}

__global__ void fill_kernel(const int* __restrict__ ei) {
    int e = blockIdx.x * 256 + threadIdx.x;
    if (e < EE) {
        int dst = ei[EE + e];
        int pos = atomicAdd(&g_cursor[dst], 1);
        g_esrc[pos] = ei[e];
    }
}

// ---------------- gather: agg[n] = h[n] + sum_{s in N(n)} h[s] ----------------
// 16 threads per node, one float4 chunk each
__global__ void gather_kernel() {
    int idx = blockIdx.x * 256 + threadIdx.x;   // grid covers NN*16 exactly
    int n = idx >> 4, c = idx & 15;
    if (n >= NN) return;
    int beg = g_rowptr[n], end = g_rowptr[n + 1];
    const float4* h4 = (const float4*)g_h;
    float4 v = h4[(size_t)n * 16 + c];
    for (int e = beg; e < end; e++) {
        int s = g_esrc[e];
        float4 a = h4[(size_t)s * 16 + c];
        v.x += a.x; v.y += a.y; v.z += a.z; v.w += a.w;
    }
    ((float4*)g_agg)[(size_t)n * 16 + c] = v;
}

// Zs layout: row r at floats [r*64, r*64+64); col k stored at slot
// ((k + 4*(r>>2)) & 63). Rotation multiple of 4 floats keeps float4 alignment;
// the 4 row-groups within a warp land on banks 4 apart -> conflict-free.

// ---------------- GEMM1: z1 = agg @ W1 + b1, plus BN stats ----------------
// 64 rows x 64 cols per block, 128 threads, thread tile = 4 rows x 8 cols
__global__ __launch_bounds__(GT, 6) void gemm1_kernel(const float* __restrict__ W,
                                                      const float* __restrict__ b) {
    extern __shared__ float smp[];
    float* Ws = smp;          // 4096 floats
    float* Zs = smp + 4096;   // 4096 floats
    int t = threadIdx.x;
    int row0 = blockIdx.x * ROWS;

    const float4* Wg = (const float4*)W;
    float4* Ws4 = (float4*)Ws;
#pragma unroll
    for (int i = 0; i < 8; i++) Ws4[t + i * GT] = Wg[t + i * GT];

#pragma unroll
    for (int i = 0; i < 8; i++) {
        int e = t + i * GT;                // 64*16 = 1024 float4s
        int r = e >> 4, c4 = e & 15;
        int gr = row0 + r;
        float4 v = make_float4(0.f, 0.f, 0.f, 0.f);
        if (gr < NN) v = ((const float4*)g_agg)[(size_t)gr * 16 + c4];
        ((float4*)(Zs + r * 64))[(c4 + (r >> 2)) & 15] = v;
    }
    __syncthreads();

    int cw = t & 7;            // col group: cols cw*8 .. cw*8+7
    int g  = t >> 3;           // row group 0..15: rows g*4 .. g*4+3
    int rowb = g * 4;
    u64 acc[4][4];
#pragma unroll
    for (int c = 0; c < 4; c++) {
        u64 bp = pack2(b[cw * 8 + c * 2], b[cw * 8 + c * 2 + 1]);
#pragma unroll
        for (int j = 0; j < 4; j++) acc[j][c] = bp;
    }

    const ulonglong2* Wsu = (const ulonglong2*)Ws;   // 16 units per k-row
#pragma unroll 8
    for (int k = 0; k < 64; k++) {
        ulonglong2 wa = Wsu[k * 16 + cw * 2];
        ulonglong2 wb = Wsu[k * 16 + cw * 2 + 1];
        int kk = (k + 4 * g) & 63;
#pragma unroll
        for (int j = 0; j < 4; j++) {
            float z = Zs[(rowb + j) * 64 + kk];
            u64 zz = pack2(z, z);
            ffma2(acc[j][0], zz, wa.x);
            ffma2(acc[j][1], zz, wa.y);
            ffma2(acc[j][2], zz, wb.x);
            ffma2(acc[j][3], zz, wb.y);
        }
    }
    __syncthreads();   // done reading Zs; reuse it for outputs

#pragma unroll
    for (int j = 0; j < 4; j++) {
        int r = rowb + j;
        int gr = row0 + r;
        float2 p0 = unpack2(acc[j][0]), p1 = unpack2(acc[j][1]);
        float2 p2 = unpack2(acc[j][2]), p3 = unpack2(acc[j][3]);
        float4 o0 = make_float4(p0.x, p0.y, p1.x, p1.y);
        float4 o1 = make_float4(p2.x, p2.y, p3.x, p3.y);
        if (gr < NN) {
            float4* og = (float4*)(g_z1 + (size_t)gr * 64 + cw * 8);
            og[0] = o0; og[1] = o1;
        } else {
            o0 = make_float4(0.f, 0.f, 0.f, 0.f);
            o1 = o0;
        }
        float4* zr = (float4*)(Zs + r * 64);
        zr[(cw * 2 + g) & 15]     = o0;
        zr[(cw * 2 + 1 + g) & 15] = o1;
    }
    __syncthreads();

    // BN stats: 128 threads, 2 row-halves x 64 cols
    {
        int col = t & 63, half = t >> 6;
        float s = 0.f, q = 0.f;
#pragma unroll 8
        for (int r = half * 32; r < half * 32 + 32; r++) {
            float v = Zs[r * 64 + ((col + 4 * (r >> 2)) & 63)];
            s += v;
            q += v * v;
        }
        atomicAdd(&g_bnsum[col], s);
        atomicAdd(&g_bnsq[col], q);
    }
}

// ---------------- GEMM2: h = relu(bn(z1)) @ W2 + b2, plus mean-pool ----------------
// BN=false is the embedding GEMM: h = x @ W_emb + b_emb
template <bool BN>
__global__ __launch_bounds__(GT, 6) void gemm2_kernel(const float* __restrict__ in,
                             const float* __restrict__ W, const float* __restrict__ b,
                             const float* __restrict__ gamma, const float* __restrict__ beta,
                             const int* __restrict__ batch, int pool_off) {
    extern __shared__ float smp[];
    float* Ws = smp;            // 4096
    float* Zs = smp + 4096;     // 4096
    float* sc = smp + 8192;     // 64
    float* sh = smp + 8256;     // 64
    int*   sb = (int*)(smp + 8320);  // 64
    int t = threadIdx.x;
    int row0 = blockIdx.x * ROWS;

    if (t < ROWS) {
        int gr = row0 + t;
        sb[t] = (gr < NN) ? batch[gr] : -1;
    }
    if (t < 64 && BN) {
        float mu = g_bnsum[t] * (1.f / NN);
        float var = g_bnsq[t] * (1.f / NN) - mu * mu;
        float rs = rsqrtf(var + 1e-5f);
        float s = gamma[t] * rs;
        sc[t] = s;
        sh[t] = beta[t] - mu * s;
    }
    const float4* Wg = (const float4*)W;
    float4* Ws4 = (float4*)Ws;
#pragma unroll
    for (int i = 0; i < 8; i++) Ws4[t + i * GT] = Wg[t + i * GT];
    __syncthreads();

#pragma unroll
    for (int i = 0; i < 8; i++) {
        int e = t + i * GT;
        int r = e >> 4, c4 = e & 15;
        int gr = row0 + r;
        float4 v = make_float4(0.f, 0.f, 0.f, 0.f);
        if (gr < NN) {
            v = ((const float4*)in)[(size_t)gr * 16 + c4];
            if (BN) {
                int k = c4 * 4;
                v.x = fmaxf(v.x * sc[k]     + sh[k],     0.f);
                v.y = fmaxf(v.y * sc[k + 1] + sh[k + 1], 0.f);
                v.z = fmaxf(v.z * sc[k + 2] + sh[k + 2], 0.f);
                v.w = fmaxf(v.w * sc[k + 3] + sh[k + 3], 0.f);
            }
        }
        ((float4*)(Zs + r * 64))[(c4 + (r >> 2)) & 15] = v;
    }
    __syncthreads();

    int cw = t & 7;
    int g  = t >> 3;
    int rowb = g * 4;
    u64 acc[4][4];
#pragma unroll
    for (int c = 0; c < 4; c++) {
        u64 bp = pack2(b[cw * 8 + c * 2], b[cw * 8 + c * 2 + 1]);
#pragma unroll
        for (int j = 0; j < 4; j++) acc[j][c] = bp;
    }

    const ulonglong2* Wsu = (const ulonglong2*)Ws;
#pragma unroll 8
    for (int k = 0; k < 64; k++) {
        ulonglong2 wa = Wsu[k * 16 + cw * 2];
        ulonglong2 wb = Wsu[k * 16 + cw * 2 + 1];
        int kk = (k + 4 * g) & 63;
#pragma unroll
        for (int j = 0; j < 4; j++) {
            float z = Zs[(rowb + j) * 64 + kk];
            u64 zz = pack2(z, z);
            ffma2(acc[j][0], zz, wa.x);
            ffma2(acc[j][1], zz, wa.y);
            ffma2(acc[j][2], zz, wb.x);
            ffma2(acc[j][3], zz, wb.y);
        }
    }
    __syncthreads();

#pragma unroll
    for (int j = 0; j < 4; j++) {
        int r = rowb + j;
        int gr = row0 + r;
        float2 p0 = unpack2(acc[j][0]), p1 = unpack2(acc[j][1]);
        float2 p2 = unpack2(acc[j][2]), p3 = unpack2(acc[j][3]);
        float4 o0 = make_float4(p0.x, p0.y, p1.x, p1.y);
        float4 o1 = make_float4(p2.x, p2.y, p3.x, p3.y);
        if (gr < NN) {
            float4* og = (float4*)(g_h + (size_t)gr * 64 + cw * 8);
            og[0] = o0; og[1] = o1;
        } else {
            o0 = make_float4(0.f, 0.f, 0.f, 0.f);
            o1 = o0;
        }
        float4* zr = (float4*)(Zs + r * 64);
        zr[(cw * 2 + g) & 15]     = o0;
        zr[(cw * 2 + 1 + g) & 15] = o1;
    }
    __syncthreads();

    // segmented mean-pool accumulation (batch sorted -> few runs per block)
    if (t < 64) {
        float s = 0.f;
        int cur = sb[0];
        for (int r = 0; r < ROWS; r++) {
            int g2 = sb[r];
            if (g2 != cur) {
                if (cur >= 0) atomicAdd(&g_pool[cur * OUTC + pool_off + t], s);
                s = 0.f;
                cur = g2;
            }
            s += Zs[r * 64 + ((t + 4 * (r >> 2)) & 63)];
        }
        if (cur >= 0) atomicAdd(&g_pool[cur * OUTC + pool_off + t], s);
    }
}

__global__ void finalize_kernel(float* __restrict__ out) {
    int i = blockIdx.x * 256 + threadIdx.x;
    if (i < GG * OUTC) {
        int g = i / OUTC;
        float c = (float)max(g_cnt[g], 1);
        out[i] = g_pool[i] / c;
    }
}

// ---------------- host ----------------
extern "C" void kernel_launch(void* const* d_in, const int* in_sizes, int n_in,
                              void* d_out, int out_size) {
    const float* x     = (const float*)d_in[0];
    const int*   ei    = (const int*)d_in[1];
    const int*   batch = (const int*)d_in[2];
    const float* W_emb = (const float*)d_in[3];
    const float* b_emb = (const float*)d_in[4];
    const float* W1    = (const float*)d_in[5];
    const float* b1    = (const float*)d_in[6];
    const float* gamma = (const float*)d_in[7];
    const float* beta  = (const float*)d_in[8];
    const float* W2    = (const float*)d_in[9];
    const float* b2    = (const float*)d_in[10];
    float* out = (float*)d_out;

    cudaFuncSetAttribute(gemm1_kernel, cudaFuncAttributeMaxDynamicSharedMemorySize, SMEM_G);
    cudaFuncSetAttribute(gemm2_kernel<false>, cudaFuncAttributeMaxDynamicSharedMemorySize, SMEM_G);
    cudaFuncSetAttribute(gemm2_kernel<true>, cudaFuncAttributeMaxDynamicSharedMemorySize, SMEM_G);

    void *p_pool, *p_cnt, *p_deg, *p_bnsum, *p_bnsq, *p_z1;
    cudaGetSymbolAddress(&p_pool, g_pool);
    cudaGetSymbolAddress(&p_cnt, g_cnt);
    cudaGetSymbolAddress(&p_deg, g_deg);
    cudaGetSymbolAddress(&p_bnsum, g_bnsum);
    cudaGetSymbolAddress(&p_bnsq, g_bnsq);
    cudaGetSymbolAddress(&p_z1, g_z1);

    cudaMemsetAsync(p_pool, 0, GG * OUTC * sizeof(float), 0);
    cudaMemsetAsync(p_cnt, 0, GG * sizeof(int), 0);
    cudaMemsetAsync(p_deg, 0, NN * sizeof(int), 0);

    count_kernel<<<(NN + 255) / 256, 256>>>(batch);

    // ---- CSR build (edge structure constant across layers) ----
    deg_kernel<<<(EE + 255) / 256, 256>>>(ei);
    scan1_kernel<<<NB, 1024>>>();
    scan2_kernel<<<1, 32>>>();
    scan3_kernel<<<(NN + 255) / 256, 256>>>();
    fill_kernel<<<(EE + 255) / 256, 256>>>(ei);

    const int GB = (NN + ROWS - 1) / ROWS;  // 1563 row-tiles

    // embedding GEMM + pool into columns [0,64)
    gemm2_kernel<false><<<GB, GT, SMEM_G>>>(x, W_emb, b_emb, nullptr, nullptr, batch, 0);

    for (int l = 0; l < 4; l++) {
        gather_kernel<<<(NN * 16 + 255) / 256, 256>>>();
        cudaMemsetAsync(p_bnsum, 0, 64 * sizeof(float), 0);
        cudaMemsetAsync(p_bnsq, 0, 64 * sizeof(float), 0);
        gemm1_kernel<<<GB, GT, SMEM_G>>>(W1 + l * 4096, b1 + l * 64);
        gemm2_kernel<true><<<GB, GT, SMEM_G>>>((const float*)p_z1, W2 + l * 4096, b2 + l * 64,
                                        gamma + l * 64, beta + l * 64, batch,
                                        (l + 1) * 64);
    }

    finalize_kernel<<<(GG * OUTC + 255) / 256, 256>>>(out);
}